// round 16
// baseline (speedup 1.0000x reference)
#include <cuda_runtime.h>
#include <cuda_fp16.h>
#include <cstdint>

#define NB 192
#define SS 512
#define EE 128
#define NROWS (NB*SS)

// ---------------- scratch (bytes) ----------------
#define B_MAT ((size_t)NROWS*EE*2)          // fp16 [NROWS,128]
#define O_Q      ((size_t)0)
#define O_K      (O_Q + B_MAT)
#define O_VT     (O_K + B_MAT)
#define O_ATTO   (O_VT + B_MAT)                       // fp32 attn out
#define O_W      (O_ATTO + (size_t)NROWS*EE*4)        // 4 weights fp16
#define O_RS     (O_W + (size_t)4*EE*EE*2)
#define O_MB     (O_RS + (size_t)NROWS*4)             // adj bitmasks, 64 B/row
#define SCRATCH_BYTES (O_MB + (size_t)NROWS*64)

__device__ __align__(1024) char g_scratch[SCRATCH_BYTES];

// ---------------- SMEM layouts ----------------
// mm kernels: A(16K) W(32K) = 48K
#define MM_A  0
#define MM_W  16384
#define MM_SMEM 49152
// fused: Q(16K) K(16K) P(8K) V(16K, both f-halves)
#define F_Q  0
#define F_K  16384
#define F_P  32768
#define F_V  40960
#define F_SMEM 57344

__device__ __forceinline__ uint32_t smem_u32(const void* p) {
    uint32_t a;
    asm("{ .reg .u64 t; cvta.to.shared.u64 t, %1; cvt.u32.u64 %0, t; }" : "=r"(a) : "l"(p));
    return a;
}

__device__ __forceinline__ uint32_t sw_off(int row, int chunk) {
    return (uint32_t)(row * 256 + ((chunk ^ (row & 7)) << 4));
}
__device__ __forceinline__ uint32_t sw_off128(int row, int chunk) {
    return (uint32_t)(row * 128 + ((chunk ^ (row & 7)) << 4));
}

#define CP_COMMIT() asm volatile("cp.async.commit_group;" ::: "memory")
#define CP_WAIT0()  asm volatile("cp.async.wait_group 0;" ::: "memory")

__device__ __forceinline__ void cp16(char* dst, const void* src) {
    uint32_t d = smem_u32(dst);
    asm volatile("cp.async.cg.shared.global [%0], [%1], 16;" :: "r"(d), "l"(src));
}

template <int ROWS>
__device__ __forceinline__ void cp_tile256(char* dst, const __half* g, int pitch) {
    #pragma unroll
    for (int it = 0; it < ROWS / 8; it++) {
        int idx = threadIdx.x + it * 128;
        int row = idx >> 4, ch = idx & 15;
        cp16(dst + sw_off(row, ch), g + (size_t)row * pitch + ch * 8);
    }
}
template <int ROWS>
__device__ __forceinline__ void cp_tile128(char* dst, const __half* g, int pitch) {
    #pragma unroll
    for (int it = 0; it < ROWS / 16; it++) {
        int idx = threadIdx.x + it * 128;
        int row = idx >> 3, ch = idx & 7;
        cp16(dst + sw_off128(row, ch), g + (size_t)row * pitch + ch * 8);
    }
}

__device__ __forceinline__ void ldsm4(uint32_t* r, uint32_t a) {
    asm volatile("ldmatrix.sync.aligned.m8n8.x4.shared.b16 {%0,%1,%2,%3}, [%4];"
                 : "=r"(r[0]), "=r"(r[1]), "=r"(r[2]), "=r"(r[3]) : "r"(a));
}
__device__ __forceinline__ void mma_f16(float* c, const uint32_t* a, const uint32_t* b) {
    asm volatile(
        "mma.sync.aligned.m16n8k16.row.col.f32.f16.f16.f32 "
        "{%0,%1,%2,%3},{%4,%5,%6,%7},{%8,%9},{%0,%1,%2,%3};"
        : "+f"(c[0]), "+f"(c[1]), "+f"(c[2]), "+f"(c[3])
        : "r"(a[0]), "r"(a[1]), "r"(a[2]), "r"(a[3]), "r"(b[0]), "r"(b[1]));
}

__device__ __forceinline__ uint32_t pack2h(float a, float b) {
    __half2 t = __floats2half2_rn(a, b);
    return *reinterpret_cast<uint32_t*>(&t);
}

// ---- LN(no affine)+ReLU of 64 fp32 rows -> swizzled fp16 tile ----
__device__ __forceinline__ void ln_stage(const float* __restrict__ src, char* dst) {
    int lane = threadIdx.x & 31, wid = threadIdx.x >> 5;
    #pragma unroll
    for (int r = 0; r < 16; r++) {
        int row = wid * 16 + r;
        float4 a = reinterpret_cast<const float4*>(src + (size_t)row * EE)[lane];
        float s = a.x + a.y + a.z + a.w;
        float q = a.x * a.x + a.y * a.y + a.z * a.z + a.w * a.w;
        #pragma unroll
        for (int o = 16; o; o >>= 1) {
            s += __shfl_xor_sync(0xffffffffu, s, o);
            q += __shfl_xor_sync(0xffffffffu, q, o);
        }
        float mean = s * (1.0f / 128.0f);
        float var  = q * (1.0f / 128.0f) - mean * mean;
        float inv  = rsqrtf(var + 1e-5f);
        float r0 = fmaxf((a.x - mean) * inv, 0.f);
        float r1 = fmaxf((a.y - mean) * inv, 0.f);
        float r2 = fmaxf((a.z - mean) * inv, 0.f);
        float r3 = fmaxf((a.w - mean) * inv, 0.f);
        uint2 uh;
        uh.x = pack2h(r0, r1); uh.y = pack2h(r2, r3);
        uint32_t off = sw_off(row, lane >> 1) + (lane & 1) * 8;
        *reinterpret_cast<uint2*>(dst + off) = uh;
    }
}

// ---- x1 MMA: A 64-row(256B), B 128-row(256B); 4 warps 32x64
__device__ __forceinline__ void mma_mm_x1(float acc[2][8][4],
                                          uint32_t sA, uint32_t sB) {
    int lane = threadIdx.x & 31, wid = threadIdx.x >> 5;
    int wm = (wid & 1) * 32, wn = (wid >> 1) * 64;
    int rsub  = ((lane >> 3) & 1) * 8 + (lane & 7);
    int khalf = (lane >> 4) & 1;
    #pragma unroll
    for (int ks = 0; ks < 8; ks++) {
        int chunk = 2 * ks + khalf;
        uint32_t a[2][4];
        #pragma unroll
        for (int mt = 0; mt < 2; mt++)
            ldsm4(a[mt], sA + sw_off(wm + mt * 16 + rsub, chunk));
        uint32_t b[8][2];
        #pragma unroll
        for (int nt2 = 0; nt2 < 4; nt2++) {
            uint32_t r[4];
            ldsm4(r, sB + sw_off(wn + nt2 * 16 + rsub, chunk));
            b[nt2 * 2][0] = r[0]; b[nt2 * 2 + 1][0] = r[1];
            b[nt2 * 2][1] = r[2]; b[nt2 * 2 + 1][1] = r[3];
        }
        #pragma unroll
        for (int mt = 0; mt < 2; mt++)
            #pragma unroll
            for (int nt = 0; nt < 8; nt++)
                mma_f16(acc[mt][nt], a[mt], b[nt]);
    }
}

// ---------------------------------------------------------------------------
// weights -> fp16
// ---------------------------------------------------------------------------
__global__ void convert_w_kernel(const float* __restrict__ w0, const float* __restrict__ w1,
                                 const float* __restrict__ w2, const float* __restrict__ w3,
                                 __half* __restrict__ wout) {
    const float* src = (blockIdx.x == 0) ? w0 : (blockIdx.x == 1) ? w1 : (blockIdx.x == 2) ? w2 : w3;
    size_t base = (size_t)blockIdx.x * EE * EE;
    for (int i = threadIdx.x; i < EE * EE; i += blockDim.x)
        wout[base + i] = __float2half_rn(src[i]);
}

// ---------------------------------------------------------------------------
// prep: adj row -> rsqrt(deg) + 512-bit mask (16 uint32 per row)
// ---------------------------------------------------------------------------
__global__ __launch_bounds__(256) void prep_kernel(const float* __restrict__ adj,
                                                   float* __restrict__ rscale,
                                                   uint32_t* __restrict__ maskbuf) {
    int row  = blockIdx.x * 8 + (threadIdx.x >> 5);
    int lane = threadIdx.x & 31;
    const float4* p = reinterpret_cast<const float4*>(adj + (size_t)row * SS) + lane * 4;
    float s = 0.f;
    uint32_t m16 = 0;
    #pragma unroll
    for (int i = 0; i < 4; i++) {
        float4 a = p[i];
        s += a.x + a.y + a.z + a.w;
        if (a.x != 0.f) m16 |= 1u << (4 * i + 0);
        if (a.y != 0.f) m16 |= 1u << (4 * i + 1);
        if (a.z != 0.f) m16 |= 1u << (4 * i + 2);
        if (a.w != 0.f) m16 |= 1u << (4 * i + 3);
    }
    float t = s;
    #pragma unroll
    for (int o = 16; o; o >>= 1) t += __shfl_xor_sync(0xffffffffu, t, o);
    if (lane == 0) rscale[row] = rsqrtf(t);
    uint32_t lo = __shfl_sync(0xffffffffu, m16, (lane & 15) * 2);
    uint32_t hi = __shfl_sync(0xffffffffu, m16, (lane & 15) * 2 + 1);
    if (lane < 16) maskbuf[(size_t)row * 16 + lane] = lo | (hi << 16);
}

// ---------------------------------------------------------------------------
// QKV merged: one CTA does Q,K,V for its 64 rows (x read + LN once).
// grid (1536), 128 threads, 3 CTAs/SM.
// ---------------------------------------------------------------------------
__global__ __launch_bounds__(128, 3) void mm_qkv_kernel(
    const float* __restrict__ x,
    const __half* __restrict__ wbuf,
    const float* __restrict__ bq, const float* __restrict__ bk, const float* __restrict__ bv,
    const float* __restrict__ rsp,
    __half* __restrict__ qq, __half* __restrict__ kk, __half* __restrict__ vt) {
    extern __shared__ __align__(1024) char smem[];
    uint32_t sb = smem_u32(smem);
    int tid = threadIdx.x, lane = tid & 31, wid = tid >> 5;
    int m0 = blockIdx.x * 64;

    cp_tile256<128>(smem + MM_W, wbuf, EE);     // W_q
    CP_COMMIT();
    ln_stage(x + (size_t)m0 * EE, smem + MM_A); // overlaps W load
    CP_WAIT0();
    __syncthreads();

    int fr = (wid & 1) * 32 + (lane >> 2);
    int fc = (wid >> 1) * 64 + ((lane & 3) << 1);

    #pragma unroll
    for (int y = 0; y < 3; y++) {
        float acc[2][8][4];
        #pragma unroll
        for (int i = 0; i < 2; i++)
            #pragma unroll
            for (int j = 0; j < 8; j++)
                #pragma unroll
                for (int t = 0; t < 4; t++) acc[i][j][t] = 0.f;
        mma_mm_x1(acc, sb + MM_A, sb + MM_W);
        __syncthreads();     // W reads done
        if (y < 2) {
            cp_tile256<128>(smem + MM_W, wbuf + (size_t)(y + 1) * EE * EE, EE);
            CP_COMMIT();
        }
        const float* bias = (y == 0) ? bq : (y == 1) ? bk : bv;

        if (y < 2) {
            __half* ob = (y == 0) ? qq : kk;
            float rsc[2][2];
            #pragma unroll
            for (int mt = 0; mt < 2; mt++)
                #pragma unroll
                for (int hh = 0; hh < 2; hh++)
                    rsc[mt][hh] = (y == 0) ? rsp[m0 + fr + mt * 16 + hh * 8] : 1.0f;
            #pragma unroll
            for (int mt = 0; mt < 2; mt++) {
                #pragma unroll
                for (int nt = 0; nt < 8; nt++) {
                    int c = fc + nt * 8;
                    float b0 = bias[c], b1 = bias[c + 1];
                    #pragma unroll
                    for (int hh = 0; hh < 2; hh++) {
                        int rr = fr + mt * 16 + hh * 8;
                        float sc = rsc[mt][hh];
                        float v0 = (acc[mt][nt][hh * 2 + 0] + b0) * sc;
                        float v1 = (acc[mt][nt][hh * 2 + 1] + b1) * sc;
                        size_t off = (size_t)(m0 + rr) * EE + c;
                        *reinterpret_cast<uint32_t*>(ob + off) = pack2h(v0, v1);
                    }
                }
            }
            CP_WAIT0();      // next W ready
            __syncthreads();
        } else {
            // V: stage transposed [f=128][m=64] into A region (A no longer needed)
            __half* sh = reinterpret_cast<__half*>(smem + MM_A);
            #pragma unroll
            for (int mt = 0; mt < 2; mt++) {
                #pragma unroll
                for (int nt = 0; nt < 8; nt++) {
                    int c = fc + nt * 8;
                    float b0 = bias[c], b1 = bias[c + 1];
                    #pragma unroll
                    for (int hh = 0; hh < 2; hh++) {
                        int rr = fr + mt * 16 + hh * 8;
                        sh[c * 64 + rr]       = __float2half_rn(acc[mt][nt][hh * 2 + 0] + b0);
                        sh[(c + 1) * 64 + rr] = __float2half_rn(acc[mt][nt][hh * 2 + 1] + b1);
                    }
                }
            }
            __syncthreads();
            int b = m0 >> 9;
            int kbase = m0 & 511;
            #pragma unroll
            for (int it = 0; it < 8; it++) {
                int idx = tid + it * 128;
                int f = idx >> 3, ch = idx & 7;
                uint4 vh = *reinterpret_cast<uint4*>(sh + f * 64 + ch * 8);
                size_t off = ((size_t)b * EE + f) * SS + kbase + ch * 8;
                *reinterpret_cast<uint4*>(vt + off) = vh;
            }
        }
    }
}

// ---------------------------------------------------------------------------
// FUSED flash attention (fp16 x1), full-row warp ownership (16m x 64n):
// warp owns rows [wid*16, wid*16+16) -> softmax stats warp-local, P warp-private.
// grid (8 qt, 192 b), 128 threads, 3 CTAs/SM.
// ---------------------------------------------------------------------------
__global__ __launch_bounds__(128, 3) void fused_attn_kernel(
    const __half* __restrict__ qp, const __half* __restrict__ kp,
    const __half* __restrict__ vtp,
    const uint32_t* __restrict__ maskbuf,
    float* __restrict__ attf) {
    extern __shared__ __align__(1024) char smem[];
    uint32_t sb = smem_u32(smem);
    int tid = threadIdx.x, lane = tid & 31, wid = tid >> 5;
    int qt = blockIdx.x, b = blockIdx.y;
    size_t ar = (size_t)b * SS + qt * 64;

    cp_tile256<64>(smem + F_Q, qp + ar * EE, EE);
    cp_tile256<64>(smem + F_K, kp + (size_t)b * SS * EE, EE);
    cp_tile128<128>(smem + F_V, vtp + (size_t)b * EE * SS, SS);
    CP_COMMIT();

    int rsub  = ((lane >> 3) & 1) * 8 + (lane & 7);
    int khalf = (lane >> 4) & 1;
    int r0  = wid * 16 + (lane >> 2);       // thread's rows: r0, r0+8
    int fcl = (lane & 3) << 1;

    float mrow[2] = { -1e30f, -1e30f }, lrow[2] = { 0.f, 0.f };
    float O[16][4];
    #pragma unroll
    for (int g = 0; g < 16; g++)
        #pragma unroll
        for (int t = 0; t < 4; t++) O[g][t] = 0.f;

    const uint2* mb2 = reinterpret_cast<const uint2*>(maskbuf);

    for (int kc = 0; kc < 8; kc++) {
        CP_WAIT0();          // K(kc) + V(kc) arrived
        __syncthreads();

        // S = Q @ K^T : per warp 16m x 64n, K=128
        float S[8][4];
        #pragma unroll
        for (int j = 0; j < 8; j++)
            #pragma unroll
            for (int t = 0; t < 4; t++) S[j][t] = 0.f;
        #pragma unroll
        for (int ks = 0; ks < 8; ks++) {
            int chunk = 2 * ks + khalf;
            uint32_t a[4];
            ldsm4(a, sb + F_Q + sw_off(wid * 16 + rsub, chunk));
            uint32_t bb[8][2];
            #pragma unroll
            for (int nt2 = 0; nt2 < 4; nt2++) {
                uint32_t r[4];
                ldsm4(r, sb + F_K + sw_off(nt2 * 16 + rsub, chunk));
                bb[nt2 * 2][0] = r[0]; bb[nt2 * 2 + 1][0] = r[1];
                bb[nt2 * 2][1] = r[2]; bb[nt2 * 2 + 1][1] = r[3];
            }
            #pragma unroll
            for (int nt = 0; nt < 8; nt++)
                mma_f16(S[nt], a, bb[nt]);
        }
        __syncthreads();     // K buffer free
        if (kc < 7) {
            cp_tile256<64>(smem + F_K, kp + ((size_t)b * SS + (kc + 1) * 64) * EE, EE);
            CP_COMMIT();
        }

        // per-row 64-bit masks (rows r0, r0+8)
        uint2 mv0 = mb2[(ar + r0) * 8 + kc];
        uint2 mv1 = mb2[(ar + r0 + 8) * 8 + kc];
        uint32_t mw[2][2] = { { mv0.x, mv0.y }, { mv1.x, mv1.y } };

        // masked max (warp-local rows)
        float cmax[2] = { -1e30f, -1e30f };
        #pragma unroll
        for (int nt = 0; nt < 8; nt++) {
            int c0 = nt * 8 + fcl;
            uint32_t w0 = mw[0][c0 >> 5], w1 = mw[1][c0 >> 5];
            int bit = c0 & 31;
            if ((w0 >> bit) & 1u)       cmax[0] = fmaxf(cmax[0], S[nt][0]);
            if ((w0 >> (bit + 1)) & 1u) cmax[0] = fmaxf(cmax[0], S[nt][1]);
            if ((w1 >> bit) & 1u)       cmax[1] = fmaxf(cmax[1], S[nt][2]);
            if ((w1 >> (bit + 1)) & 1u) cmax[1] = fmaxf(cmax[1], S[nt][3]);
        }
        #pragma unroll
        for (int ri = 0; ri < 2; ri++) {
            cmax[ri] = fmaxf(cmax[ri], __shfl_xor_sync(0xffffffffu, cmax[ri], 1));
            cmax[ri] = fmaxf(cmax[ri], __shfl_xor_sync(0xffffffffu, cmax[ri], 2));
        }
        float fscale[2], mn[2];
        #pragma unroll
        for (int ri = 0; ri < 2; ri++) {
            mn[ri] = fmaxf(mrow[ri], cmax[ri]);
            fscale[ri] = __expf(mrow[ri] - mn[ri]);
            mrow[ri] = mn[ri];
        }

        // exp + write P (warp-private rows) + row sums
        float csum[2] = { 0.f, 0.f };
        #pragma unroll
        for (int nt = 0; nt < 8; nt++) {
            int c0 = nt * 8 + fcl;
            uint32_t w0 = mw[0][c0 >> 5], w1 = mw[1][c0 >> 5];
            int bit = c0 & 31;
            float p0 = ((w0 >> bit) & 1u)       ? __expf(S[nt][0] - mn[0]) : 0.f;
            float p1 = ((w0 >> (bit + 1)) & 1u) ? __expf(S[nt][1] - mn[0]) : 0.f;
            float p2 = ((w1 >> bit) & 1u)       ? __expf(S[nt][2] - mn[1]) : 0.f;
            float p3 = ((w1 >> (bit + 1)) & 1u) ? __expf(S[nt][3] - mn[1]) : 0.f;
            csum[0] += p0 + p1;
            csum[1] += p2 + p3;
            uint32_t off0 = sw_off128(r0,     c0 >> 3) + (c0 & 7) * 2;
            uint32_t off1 = sw_off128(r0 + 8, c0 >> 3) + (c0 & 7) * 2;
            *reinterpret_cast<uint32_t*>(smem + F_P + off0) = pack2h(p0, p1);
            *reinterpret_cast<uint32_t*>(smem + F_P + off1) = pack2h(p2, p3);
        }
        #pragma unroll
        for (int ri = 0; ri < 2; ri++) {
            csum[ri] += __shfl_xor_sync(0xffffffffu, csum[ri], 1);
            csum[ri] += __shfl_xor_sync(0xffffffffu, csum[ri], 2);
            lrow[ri] = lrow[ri] * fscale[ri] + csum[ri];
        }

        // rescale O
        #pragma unroll
        for (int g = 0; g < 16; g++) {
            O[g][0] *= fscale[0]; O[g][1] *= fscale[0];
            O[g][2] *= fscale[1]; O[g][3] *= fscale[1];
        }

        __syncwarp();        // P stores visible to own warp's ldmatrix

        // O += P @ V^T : per warp 16m x 128f, K=64 (two f-halves)
        #pragma unroll
        for (int h = 0; h < 2; h++) {
            uint32_t sV = sb + F_V + h * 8192;
            #pragma unroll
            for (int ks = 0; ks < 4; ks++) {
                int chunk = 2 * ks + khalf;
                uint32_t a[4];
                ldsm4(a, sb + F_P + sw_off128(wid * 16 + rsub, chunk));
                uint32_t bb[8][2];
                #pragma unroll
                for (int nt2 = 0; nt2 < 4; nt2++) {
                    uint32_t r[4];
                    ldsm4(r, sV + sw_off128(nt2 * 16 + rsub, chunk));
                    bb[nt2 * 2][0] = r[0]; bb[nt2 * 2 + 1][0] = r[1];
                    bb[nt2 * 2][1] = r[2]; bb[nt2 * 2 + 1][1] = r[3];
                }
                #pragma unroll
                for (int nt = 0; nt < 8; nt++)
                    mma_f16(O[h * 8 + nt], a, bb[nt]);
            }
        }
        __syncthreads();     // V buffer free
        if (kc < 7) {
            cp_tile128<128>(smem + F_V, vtp + (size_t)b * EE * SS + (kc + 1) * 64, SS);
            CP_COMMIT();
        }
    }

    // epilogue: normalize + store
    float inv0 = 1.f / lrow[0], inv1 = 1.f / lrow[1];
    size_t gm0 = (ar + r0) * EE, gm1 = (ar + r0 + 8) * EE;
    #pragma unroll
    for (int g = 0; g < 16; g++) {
        int c = ((g >> 3) << 6) + (g & 7) * 8 + fcl;
        *reinterpret_cast<float2*>(attf + gm0 + c) =
            make_float2(O[g][0] * inv0, O[g][1] * inv0);
        *reinterpret_cast<float2*>(attf + gm1 + c) =
            make_float2(O[g][2] * inv1, O[g][3] * inv1);
    }
}

// ---------------------------------------------------------------------------
// out projection (fused LN, fp16 x1): out = x + LN_ReLU(attf) @ Wo^T + bo.
// ---------------------------------------------------------------------------
__global__ __launch_bounds__(128, 3) void mm_out_kernel(
    const float* __restrict__ attf,
    const __half* __restrict__ wo,
    const float* __restrict__ bo, const float* __restrict__ x,
    float* __restrict__ out) {
    extern __shared__ __align__(1024) char smem[];
    uint32_t sb = smem_u32(smem);
    int tid = threadIdx.x, lane = tid & 31, wid = tid >> 5;
    int m0 = blockIdx.x * 64;

    cp_tile256<128>(smem + MM_W, wo, EE);
    CP_COMMIT();
    ln_stage(attf + (size_t)m0 * EE, smem + MM_A);
    CP_WAIT0();
    __syncthreads();

    float acc[2][8][4];
    #pragma unroll
    for (int i = 0; i < 2; i++)
        #pragma unroll
        for (int j = 0; j < 8; j++)
            #pragma unroll
            for (int t = 0; t < 4; t++) acc[i][j][t] = 0.f;
    mma_mm_x1(acc, sb + MM_A, sb + MM_W);

    int fr = (wid & 1) * 32 + (lane >> 2);
    int fc = (wid >> 1) * 64 + ((lane & 3) << 1);
    #pragma unroll
    for (int mt = 0; mt < 2; mt++) {
        #pragma unroll
        for (int hh = 0; hh < 2; hh++) {
            size_t gm = (size_t)(m0 + fr + mt * 16 + hh * 8);
            #pragma unroll
            for (int nt = 0; nt < 8; nt++) {
                int c = fc + nt * 8;
                float2 xr = *reinterpret_cast<const float2*>(x + gm * EE + c);
                float v0 = acc[mt][nt][hh * 2 + 0] + bo[c] + xr.x;
                float v1 = acc[mt][nt][hh * 2 + 1] + bo[c + 1] + xr.y;
                *reinterpret_cast<float2*>(out + gm * EE + c) = make_float2(v0, v1);
            }
        }
    }
}

// ---------------------------------------------------------------------------
extern "C" void kernel_launch(void* const* d_in, const int* in_sizes, int n_in,
                              void* d_out, int out_size) {
    const float* x   = (const float*)d_in[0];
    const float* adj = (const float*)d_in[1];
    const float* Wq  = (const float*)d_in[2];
    const float* bq  = (const float*)d_in[3];
    const float* Wk  = (const float*)d_in[4];
    const float* bk  = (const float*)d_in[5];
    const float* Wv  = (const float*)d_in[6];
    const float* bv  = (const float*)d_in[7];
    const float* Wo  = (const float*)d_in[8];
    const float* bo  = (const float*)d_in[9];
    float* out = (float*)d_out;

    char* s = nullptr;
    cudaGetSymbolAddress((void**)&s, g_scratch);
    __half* qbuf = (__half*)(s + O_Q);
    __half* kbuf = (__half*)(s + O_K);
    __half* vt   = (__half*)(s + O_VT);
    float*  attf = (float*)(s + O_ATTO);
    __half* wbuf = (__half*)(s + O_W);
    float*  rs   = (float*)(s + O_RS);
    uint32_t* mb = (uint32_t*)(s + O_MB);

    cudaFuncSetAttribute(mm_qkv_kernel,     cudaFuncAttributeMaxDynamicSharedMemorySize, MM_SMEM);
    cudaFuncSetAttribute(fused_attn_kernel, cudaFuncAttributeMaxDynamicSharedMemorySize, F_SMEM);
    cudaFuncSetAttribute(mm_out_kernel,     cudaFuncAttributeMaxDynamicSharedMemorySize, MM_SMEM);

    convert_w_kernel<<<4, 256>>>(Wq, Wk, Wv, Wo, wbuf);
    prep_kernel<<<NROWS / 8, 256>>>(adj, rs, mb);
    mm_qkv_kernel<<<NROWS / 64, 128, MM_SMEM>>>(
        x, wbuf, bq, bk, bv, rs, qbuf, kbuf, vt);
    fused_attn_kernel<<<dim3(8, NB), 128, F_SMEM>>>(
        qbuf, kbuf, vt, mb, attf);
    mm_out_kernel<<<NROWS / 64, 128, MM_SMEM>>>(
        attf, wbuf + 3 * EE * EE, bo, x, out);
}